// round 16
// baseline (speedup 1.0000x reference)
#include <cuda_runtime.h>
#include <math.h>

// Problem constants
#define NUM_R 8
#define KLEN  128
#define HID   32
#define LREC  4096
#define KP1   (KLEN + 1)
#define MAXB1 16

// Base table (kb==128 coefficients): g_T[b1][r][h] = (vy*(A + inv*B), vy*A)
__device__ float2 g_T[MAXB1][NUM_R][HID];
// Raw prefix tables (PA, PB): general fallback
__device__ float  g_P[NUM_R][KP1][2][HID];
// Delta table vs k=128: g_D[r][k][0][h] = PA[k]-PA[128], [1][h] = PB[k]-PB[128]
// (row k==128 is exactly zero -> used as the "no correction" slot)
__device__ float  g_D[NUM_R][KP1][2][HID];
// vy[b1][r]
__device__ float  g_vy[MAXB1][NUM_R];

// Table build: ONE block per r (8 blocks).
__global__ void __launch_bounds__(256) prep_kernel(
    const float* __restrict__ W1, const float* __restrict__ rec, int nb1)
{
    __shared__ float sA[KP1][HID];
    __shared__ float sB[KP1][HID];
    __shared__ float sTA[8][HID];
    __shared__ float sTB[8][HID];
    __shared__ float svy[MAXB1];
    int r   = blockIdx.x;
    int h   = threadIdx.x & 31;
    int seg = threadIdx.x >> 5;   // 0..7, 16 k's each
    const float inv = 1.0f / 16384.0f;

    if ((int)threadIdx.x < nb1) {
        const float* rr = rec + (size_t)(threadIdx.x * NUM_R + r) * LREC;
        svy[threadIdx.x] = 0.5f * rr[2047] + 0.5f * rr[2048];
    }

    int k0 = seg * 16;
    float a = 0.f, b = 0.f;
    if (seg == 0) { sA[0][h] = 0.f; sB[0][h] = 0.f; }
#pragma unroll
    for (int j = 0; j < 16; ++j) {
        int k = k0 + j;
        float w = W1[(r * KLEN + k) * HID + h];
        a += w;
        b += (float)k * w;
        sA[k + 1][h] = a;
        sB[k + 1][h] = b;
    }
    sTA[seg][h] = a;
    sTB[seg][h] = b;
    __syncthreads();

    float offA = 0.f, offB = 0.f;
    for (int s = 0; s < seg; ++s) { offA += sTA[s][h]; offB += sTB[s][h]; }
    if (seg > 0) {
#pragma unroll
        for (int j = 0; j < 16; ++j) {
            int k = k0 + j;
            sA[k + 1][h] += offA;
            sB[k + 1][h] += offB;
        }
    }
    __syncthreads();

    if ((int)threadIdx.x < nb1) g_vy[threadIdx.x][r] = svy[threadIdx.x];

    float Aend = sA[KLEN][h];
    float Bend = sB[KLEN][h];
    for (int k = seg; k < KP1; k += 8) {
        float pa = sA[k][h], pb = sB[k][h];
        g_P[r][k][0][h] = pa;
        g_P[r][k][1][h] = pb;
        g_D[r][k][0][h] = pa - Aend;
        g_D[r][k][1][h] = pb - Bend;
    }
    if (seg == 0) {
        float base = fmaf(inv, Bend, Aend);
        for (int b1 = 0; b1 < nb1; ++b1) {
            float vy = svy[b1];
            g_T[b1][r][h] = make_float2(vy * base, vy * Aend);
        }
    }
    asm volatile("griddepcontrol.launch_dependents;" ::: "memory");
}

__device__ __forceinline__ float fast_dist(float dx, float dy, float dz) {
    float d2 = fmaf(dx, dx, fmaf(dy, dy, dz * dz));
    return d2 * __frsqrt_rn(fmaxf(d2, 1e-38f));
}

// Thread-per-sample main kernel. Each thread computes its own geometry (8
// receivers), then loops h=0..31 with block-uniform coefficients in smem:
//   acc_h = sBB[h] + sum_r u_r * sCY[h][r]  (+ optional one-slot correction)
//   pred += relu(acc_h) * sW2[h]
// No warp collectives in the hot path; output stores are fully coalesced.
__global__ void __launch_bounds__(256) tof_kernel(
    const float* __restrict__ sloc,   // (B1*B2, 3)
    const float* __restrict__ emit,   // (3,)
    const float* __restrict__ rloc,   // (R, 3)
    const float* __restrict__ b1v,    // (HID,)
    const float* __restrict__ W2,     // (HID,)
    const float* __restrict__ b2v,    // (1,)
    float* __restrict__ out,          // (B1*B2,)
    int total, int b2n, int b1shift)
{
    __shared__ __align__(16) float sCY[HID][NUM_R];
    __shared__ float sBB[HID];
    __shared__ float sW2[HID];

    int tid   = threadIdx.x;
    int sbase = (int)blockIdx.x * 256;
    int s     = sbase + tid;
    const float inv  = 1.0f / 16384.0f;
    const float inv2 = 2.0f / 16384.0f;
    const float SCALE = 96000.0f / 343.0f;

    int b1blk = (b1shift >= 0) ? (sbase >> b1shift)
                               : (int)((unsigned)sbase / (unsigned)b2n);
    bool valid = s < total;

    // ---- Phase 1: per-thread geometry (overlaps prep via PDL) ----
    float u[NUM_R];
    const float* slotPtr = &g_D[0][KLEN][0][0];   // zero row
    int   slotR = 0;
    float slotU = 0.f;
    int   nslot = 0;
    bool  okr = true;
#pragma unroll
    for (int r = 0; r < NUM_R; ++r) u[r] = 0.f;

    if (valid) {
        const float* p = sloc + (size_t)s * 3;
        float sx = p[0], sy = p[1], sz = p[2];
        float de = fast_dist(sx - emit[0], sy - emit[1], sz - emit[2]);
        int b1s = (b1shift >= 0) ? (s >> b1shift)
                                 : (int)((unsigned)s / (unsigned)b2n);
        okr = (b1s == b1blk);
#pragma unroll
        for (int r = 0; r < NUM_R; ++r) {
            const float* rp = rloc + r * 3;
            float dr = fast_dist(sx - rp[0], sy - rp[1], sz - rp[2]);
            int cs = __float2int_rn((de + dr) * SCALE) - (KLEN / 2);
            int m0 = 4 * cs - 8192;
            u[r] = (float)m0 * inv;
            okr = okr && (m0 >= -16384) && (m0 <= 16384 - KLEN);
            if (m0 > -KLEN) {                       // kb != 128
                int kb = max(min(-m0, KLEN), 0);
                slotPtr = &g_D[r][kb][0][0];
                slotR = r;
                slotU = u[r];
                ++nslot;
            }
        }
    }
    bool general = valid && (!okr || nslot > 1);

    // Wait for prep's tables (PDL). No-op when launched without PDL.
    asm volatile("griddepcontrol.wait;" ::: "memory");

    // Slot coefficients (need g_vy -> after wait)
    float cu = 0.f, cb = 0.f;
    if (nslot == 1 && !general) {
        float vy = g_vy[b1blk][slotR];
        cu = 2.0f * slotU * vy;
        cb = inv2 * vy;
    }

    // ---- Stage block-uniform coefficients ----
    {
        int h = tid >> 3, r = tid & 7;
        sCY[h][r] = g_T[b1blk][r][h].y;
    }
    if (tid < HID) {
        float bb = b1v[tid];
#pragma unroll
        for (int r = 0; r < NUM_R; ++r) bb += g_T[b1blk][r][tid].x;
        sBB[tid] = bb;
        sW2[tid] = W2[tid];
    }
    __syncthreads();

    unsigned slotb = __ballot_sync(0xffffffffu, nslot > 0 && !general && valid);
    float b2s = b2v[0];

    if (valid && !general) {
        float p0 = 0.f, p1 = 0.f;
        if (slotb == 0) {
            // clean loop: no correction anywhere in this warp
#pragma unroll
            for (int h = 0; h < HID; ++h) {
                float4 c0 = *(const float4*)&sCY[h][0];
                float4 c1 = *(const float4*)&sCY[h][4];
                float acc = sBB[h];
                acc = fmaf(u[0], c0.x, acc); acc = fmaf(u[1], c0.y, acc);
                acc = fmaf(u[2], c0.z, acc); acc = fmaf(u[3], c0.w, acc);
                acc = fmaf(u[4], c1.x, acc); acc = fmaf(u[5], c1.y, acc);
                acc = fmaf(u[6], c1.z, acc); acc = fmaf(u[7], c1.w, acc);
                float rel = fmaxf(acc, 0.f);
                if (h & 1) p1 = fmaf(rel, sW2[h], p1);
                else       p0 = fmaf(rel, sW2[h], p0);
            }
        } else {
            // slot loop: one correction row per thread (zero row if clean)
#pragma unroll
            for (int h = 0; h < HID; ++h) {
                float4 c0 = *(const float4*)&sCY[h][0];
                float4 c1 = *(const float4*)&sCY[h][4];
                float da = slotPtr[h];
                float db = slotPtr[HID + h];
                float acc = sBB[h];
                acc = fmaf(u[0], c0.x, acc); acc = fmaf(u[1], c0.y, acc);
                acc = fmaf(u[2], c0.z, acc); acc = fmaf(u[3], c0.w, acc);
                acc = fmaf(u[4], c1.x, acc); acc = fmaf(u[5], c1.y, acc);
                acc = fmaf(u[6], c1.z, acc); acc = fmaf(u[7], c1.w, acc);
                acc = fmaf(cu, da, acc);
                acc = fmaf(cb, db, acc);
                float rel = fmaxf(acc, 0.f);
                if (h & 1) p1 = fmaf(rel, sW2[h], p1);
                else       p0 = fmaf(rel, sW2[h], p0);
            }
        }
        out[s] = p0 + p1 + b2s;
    } else if (general) {
        // ---- General (rare) path: full clamped two-segment form ----
        int b1s = (b1shift >= 0) ? (s >> b1shift)
                                 : (int)((unsigned)s / (unsigned)b2n);
        int ka[NUM_R], kb[NUM_R], kd[NUM_R];
        float m0f[NUM_R], vyA[NUM_R];
#pragma unroll
        for (int r = 0; r < NUM_R; ++r) {
            int m0 = __float2int_rn(u[r] * 16384.0f);
            ka[r] = max(min(-16384 - m0, KLEN), 0);
            kb[r] = max(min(-m0,          KLEN), 0);
            kd[r] = max(min(16384 - m0,   KLEN), 0);
            m0f[r] = (float)m0;
            vyA[r] = g_vy[b1s][r];
        }
        float pred = 0.f;
        for (int h = 0; h < HID; ++h) {
            float acc = b1v[h];
#pragma unroll
            for (int r = 0; r < NUM_R; ++r) {
                if (kb[r] > ka[r]) {
                    float pa = g_P[r][kb[r]][0][h] - g_P[r][ka[r]][0][h];
                    float pb = g_P[r][kb[r]][1][h] - g_P[r][ka[r]][1][h];
                    acc += vyA[r] * (fmaf(m0f[r], inv, 1.0f) * pa + inv * pb);
                }
                if (kd[r] > kb[r]) {
                    float pa = g_P[r][kd[r]][0][h] - g_P[r][kb[r]][0][h];
                    float pb = g_P[r][kd[r]][1][h] - g_P[r][kb[r]][1][h];
                    acc += vyA[r] * (fmaf(-m0f[r], inv, 1.0f) * pa - inv * pb);
                }
            }
            pred = fmaf(fmaxf(acc, 0.f), W2[h], pred);
        }
        out[s] = pred + b2s;
    }
}

extern "C" void kernel_launch(void* const* d_in, const int* in_sizes, int n_in,
                              void* d_out, int out_size) {
    const float* rec  = (const float*)d_in[0];
    const float* sloc = (const float*)d_in[1];
    const float* emit = (const float*)d_in[2];
    const float* rloc = (const float*)d_in[3];
    const float* W1   = (const float*)d_in[4];
    const float* b1v  = (const float*)d_in[5];
    const float* W2   = (const float*)d_in[6];
    const float* b2v  = (const float*)d_in[7];
    float* out = (float*)d_out;

    int nb1 = in_sizes[0] / (NUM_R * LREC);       // B1
    if (nb1 < 1) nb1 = 1;
    if (nb1 > MAXB1) nb1 = MAXB1;
    int total = out_size;                         // B1*B2 samples
    int b2n = total / nb1;

    int b1shift = -1;
    if (b2n > 0 && (b2n & (b2n - 1)) == 0) {
        b1shift = 0;
        while ((1 << b1shift) != b2n) ++b1shift;
    }

    prep_kernel<<<NUM_R, 256>>>(W1, rec, nb1);

    int blocks = (total + 255) / 256;             // one thread per sample

    // PDL launch: tof's geometry overlaps prep; fallback to plain launch.
    cudaLaunchConfig_t cfg = {};
    cfg.gridDim  = dim3((unsigned)blocks, 1, 1);
    cfg.blockDim = dim3(256, 1, 1);
    cfg.dynamicSmemBytes = 0;
    cfg.stream = 0;
    cudaLaunchAttribute at[1];
    at[0].id = cudaLaunchAttributeProgrammaticStreamSerialization;
    at[0].val.programmaticStreamSerializationAllowed = 1;
    cfg.attrs = at;
    cfg.numAttrs = 1;
    cudaError_t e = cudaLaunchKernelEx(&cfg, tof_kernel,
                                       sloc, emit, rloc, b1v, W2, b2v, out,
                                       total, b2n, b1shift);
    if (e != cudaSuccess) {
        (void)cudaGetLastError();   // clear sticky error
        tof_kernel<<<blocks, 256>>>(sloc, emit, rloc, b1v, W2, b2v, out,
                                    total, b2n, b1shift);
    }
}

// round 17
// speedup vs baseline: 1.8784x; 1.8784x over previous
#include <cuda_runtime.h>
#include <math.h>

// Problem constants
#define NUM_R 8
#define KLEN  128
#define HID   32
#define LREC  4096
#define KP1   (KLEN + 1)
#define MAXB1 16

// Fast-path folded table: contribution of receiver r, batch b1:
//   S = c.x + u * c.y   (vy baked in)
__device__ float2 g_C[MAXB1][NUM_R][KP1][HID];
// Raw prefix tables (PA, PB) for the general fallback path
__device__ float  g_P[NUM_R][KP1][2][HID];
// vy[b1][r] for the fallback path
__device__ float  g_vy[MAXB1][NUM_R];

// Lean table build: ONE block per r (8 blocks). Prefix sums are b1-
// independent (smem scratch); the b1 axis only scales by vy in-loop.
__global__ void __launch_bounds__(256) prep_kernel(
    const float* __restrict__ W1, const float* __restrict__ rec, int nb1)
{
    __shared__ float sA[KP1][HID];
    __shared__ float sB[KP1][HID];
    __shared__ float sTA[8][HID];
    __shared__ float sTB[8][HID];
    __shared__ float svy[MAXB1];
    int r   = blockIdx.x;
    int h   = threadIdx.x & 31;
    int seg = threadIdx.x >> 5;   // 0..7, 16 k's each
    const float inv  = 1.0f / 16384.0f;
    const float inv2 = 2.0f / 16384.0f;

    // vy for every b1 (independent of the scan; covered by first barrier)
    if ((int)threadIdx.x < nb1) {
        const float* rr = rec + (size_t)(threadIdx.x * NUM_R + r) * LREC;
        svy[threadIdx.x] = 0.5f * rr[2047] + 0.5f * rr[2048];
    }

    int k0 = seg * 16;
    float a = 0.f, b = 0.f;
    if (seg == 0) { sA[0][h] = 0.f; sB[0][h] = 0.f; }
#pragma unroll
    for (int j = 0; j < 16; ++j) {
        int k = k0 + j;
        float w = W1[(r * KLEN + k) * HID + h];
        a += w;
        b += (float)k * w;
        sA[k + 1][h] = a;
        sB[k + 1][h] = b;
    }
    sTA[seg][h] = a;
    sTB[seg][h] = b;
    __syncthreads();

    float offA = 0.f, offB = 0.f;
    for (int s = 0; s < seg; ++s) { offA += sTA[s][h]; offB += sTB[s][h]; }
    if (seg > 0) {
#pragma unroll
        for (int j = 0; j < 16; ++j) {
            int k = k0 + j;
            sA[k + 1][h] += offA;
            sB[k + 1][h] += offB;
        }
    }
    __syncthreads();

    if ((int)threadIdx.x < nb1) g_vy[threadIdx.x][r] = svy[threadIdx.x];

    float Aend = sA[KLEN][h];
    float Bend = sB[KLEN][h];
    float Base = fmaf(-inv, Bend, Aend);
    for (int k = seg; k < KP1; k += 8) {
        float pa = sA[k][h], pb = sB[k][h];
        g_P[r][k][0][h] = pa;
        g_P[r][k][1][h] = pb;
        float t1 = fmaf(inv2, pb, Base);       // b1-independent parts
        float t2 = fmaf(2.0f, pa, -Aend);
        for (int b1 = 0; b1 < nb1; ++b1) {
            float vy = svy[b1];
            g_C[b1][r][k][h] = make_float2(vy * t1, vy * t2);
        }
    }
    // Signal PDL dependents (tof) that our global stores are ready.
    asm volatile("griddepcontrol.launch_dependents;" ::: "memory");
}

// Warp-autonomous main kernel (R12 verbatim — measured best, 12.1us):
// each warp owns 8 samples = 2 tiles of 4. Lane layout per tile:
// s_loc = lane>>3 (0..3), r = lane&7. No block-wide barriers.
__global__ void __launch_bounds__(256) tof_kernel(
    const float* __restrict__ sloc,   // (B1*B2, 3)
    const float* __restrict__ emit,   // (3,)
    const float* __restrict__ rloc,   // (R, 3)
    const float* __restrict__ b1v,    // (HID,)
    const float* __restrict__ W2,     // (HID,)
    const float* __restrict__ b2v,    // (1,)
    float* __restrict__ out,          // (B1*B2,)
    int total, int b2n, int b1shift)
{
    __shared__ __align__(16) float2 sg[8][2][4][NUM_R];

    int tid  = threadIdx.x;
    int wid  = tid >> 5;
    int lane = tid & 31;
    int s_loc = lane >> 3;
    int r     = lane & 7;
    int s_base = ((int)blockIdx.x * 8 + wid) * 8;
    const float inv = 1.0f / 16384.0f;
    const float SCALE = 96000.0f / 343.0f;

    int b1w = (b1shift >= 0) ? (s_base >> b1shift)
                             : (int)((unsigned)s_base / (unsigned)b2n);

    // ---- Phase 1: issue ALL coordinate loads first (max MLP) ----
    float cxv[2], cyv[2], czv[2];
    bool  vv[2];
#pragma unroll
    for (int t = 0; t < 2; ++t) {
        int s = s_base + t * 4 + s_loc;
        vv[t] = s < total;
        cxv[t] = 0.f; cyv[t] = 0.f; czv[t] = 0.f;
        if (vv[t]) {
            const float* p = sloc + (size_t)s * 3;
            cxv[t] = p[0]; cyv[t] = p[1]; czv[t] = p[2];
        }
    }
    float ex = emit[0], ey = emit[1], ez = emit[2];
    const float* rp = rloc + r * 3;
    float rx = rp[0], ry = rp[1], rz = rp[2];
    float blane = b1v[lane];
    float wlane = W2[lane];
    float b2s   = b2v[0];

    // ---- geometry per tile ----
    bool ok = true;
    bool corr[2];
#pragma unroll
    for (int t = 0; t < 2; ++t) {
        int offv = 0; float uv = 0.f;
        corr[t] = false;
        if (vv[t]) {
            int s = s_base + t * 4 + s_loc;
            float dx = cxv[t] - ex, dy = cyv[t] - ey, dz = czv[t] - ez;
            float de = sqrtf(dx * dx + dy * dy + dz * dz);
            float qx = cxv[t] - rx, qy = cyv[t] - ry, qz = czv[t] - rz;
            float dr = sqrtf(qx * qx + qy * qy + qz * qz);
            int cs = (int)rintf((de + dr) * SCALE) - (KLEN / 2);
            int m0 = 4 * cs - 8192;
            int kb = max(min(-m0, KLEN), 0);
            int b1 = (b1shift >= 0) ? (s >> b1shift)
                                    : (int)((unsigned)s / (unsigned)b2n);
            ok = ok && (m0 >= -16384) && (m0 <= 16384 - KLEN) && (b1 == b1w);
            corr[t] = (kb != KLEN);
            offv = ((b1 * NUM_R + r) * KP1 + kb) * (HID * 8);
            uv = (float)m0 * inv;
        }
        sg[wid][t][s_loc][r] = make_float2(__int_as_float(offv), uv);
    }
    bool fast = __all_sync(0xffffffffu, ok);
    unsigned bal0 = __ballot_sync(0xffffffffu, corr[0]);
    unsigned bal1 = __ballot_sync(0xffffffffu, corr[1]);
    (void)bal0; (void)bal1;
    __syncwarp();
    // Wait for prep's tables (PDL). No-op when launched without PDL.
    asm volatile("griddepcontrol.wait;" ::: "memory");

    const char* basep = (const char*)(&g_C[0][0][0][0]) + lane * 8;

    if (fast) {
#pragma unroll
        for (int t = 0; t < 2; ++t) {
            int s0g = s_base + t * 4;
            float acc0 = 0.f, acc1 = 0.f, acc2 = 0.f, acc3 = 0.f;

            const float4* row0 = (const float4*)&sg[wid][t][0][0];
            const float4* row1 = (const float4*)&sg[wid][t][1][0];
            const float4* row2 = (const float4*)&sg[wid][t][2][0];
            const float4* row3 = (const float4*)&sg[wid][t][3][0];
#pragma unroll
            for (int r2 = 0; r2 < 4; ++r2) {   // two receivers per iter
                float4 a = row0[r2], b = row1[r2], c = row2[r2], d = row3[r2];
                float2 ca0 = *(const float2*)(basep + __float_as_int(a.x));
                float2 cb0 = *(const float2*)(basep + __float_as_int(b.x));
                float2 cc0 = *(const float2*)(basep + __float_as_int(c.x));
                float2 cd0 = *(const float2*)(basep + __float_as_int(d.x));
                float2 ca1 = *(const float2*)(basep + __float_as_int(a.z));
                float2 cb1 = *(const float2*)(basep + __float_as_int(b.z));
                float2 cc1 = *(const float2*)(basep + __float_as_int(c.z));
                float2 cd1 = *(const float2*)(basep + __float_as_int(d.z));
                acc0 = fmaf(a.y, ca0.y, acc0 + ca0.x);
                acc1 = fmaf(b.y, cb0.y, acc1 + cb0.x);
                acc2 = fmaf(c.y, cc0.y, acc2 + cc0.x);
                acc3 = fmaf(d.y, cd0.y, acc3 + cd0.x);
                acc0 = fmaf(a.w, ca1.y, acc0 + ca1.x);
                acc1 = fmaf(b.w, cb1.y, acc1 + cb1.x);
                acc2 = fmaf(c.w, cc1.y, acc2 + cc1.x);
                acc3 = fmaf(d.w, cd1.y, acc3 + cd1.x);
            }

            // relu + W2 dot, merged 4-sample warp reduction (proven form:
            // all shuffles unconditional; ternaries select lane-local sums)
            float c0 = fmaxf(acc0 + blane, 0.f) * wlane;
            float c1 = fmaxf(acc1 + blane, 0.f) * wlane;
            float c2 = fmaxf(acc2 + blane, 0.f) * wlane;
            float c3 = fmaxf(acc3 + blane, 0.f) * wlane;

            float t0 = __shfl_xor_sync(0xffffffffu, c0, 16);
            float t1 = __shfl_xor_sync(0xffffffffu, c1, 16);
            float t2 = __shfl_xor_sync(0xffffffffu, c2, 16);
            float t3 = __shfl_xor_sync(0xffffffffu, c3, 16);
            bool lo16 = lane < 16;
            float v = lo16 ? (c0 + t0) : (c1 + t1);
            float w = lo16 ? (c2 + t2) : (c3 + t3);
            float tv = __shfl_xor_sync(0xffffffffu, v, 8);
            float tw = __shfl_xor_sync(0xffffffffu, w, 8);
            float z = ((lane & 8) == 0) ? (v + tv) : (w + tw);
            z += __shfl_xor_sync(0xffffffffu, z, 4);
            z += __shfl_xor_sync(0xffffffffu, z, 2);
            z += __shfl_xor_sync(0xffffffffu, z, 1);

            if ((lane & 7) == 0) {
                int g = ((lane >> 2) & 2) | (lane >> 4); // 0->0,8->2,16->1,24->3
                int idx = s0g + g;
                if (idx < total) out[idx] = z + b2s;
            }
        }
    } else {
        // ---- General fallback (rare): full clamped two-segment form ----
#pragma unroll
        for (int t = 0; t < 2; ++t) {
            int s0g = s_base + t * 4;
            float accs[4];
            for (int j = 0; j < 4; ++j) {
                accs[j] = 0.f;
                int sample = s0g + j;
                if (sample >= total) continue;
                int b1 = (b1shift >= 0) ? (sample >> b1shift)
                                        : (int)((unsigned)sample / (unsigned)b2n);
                float a = 0.f;
                for (int rr = 0; rr < NUM_R; ++rr) {
                    float2 g = sg[wid][t][j][rr];
                    int m0 = __float2int_rn(g.y * 16384.0f);
                    float vy = g_vy[b1][rr];
                    int ka = max(min(-16384 - m0, KLEN), 0);
                    int kb = max(min(-m0,          KLEN), 0);
                    int kd = max(min(16384 - m0,   KLEN), 0);
                    float m0f = (float)m0;
                    if (kb > ka) {
                        float pa = g_P[rr][kb][0][lane] - g_P[rr][ka][0][lane];
                        float pb = g_P[rr][kb][1][lane] - g_P[rr][ka][1][lane];
                        a += vy * (fmaf(m0f, inv, 1.0f) * pa + inv * pb);
                    }
                    if (kd > kb) {
                        float pa = g_P[rr][kd][0][lane] - g_P[rr][kb][0][lane];
                        float pb = g_P[rr][kd][1][lane] - g_P[rr][kb][1][lane];
                        a += vy * (fmaf(-m0f, inv, 1.0f) * pa - inv * pb);
                    }
                }
                accs[j] = a;
            }
            float c0 = fmaxf(accs[0] + blane, 0.f) * wlane;
            float c1 = fmaxf(accs[1] + blane, 0.f) * wlane;
            float c2 = fmaxf(accs[2] + blane, 0.f) * wlane;
            float c3 = fmaxf(accs[3] + blane, 0.f) * wlane;

            float t0 = __shfl_xor_sync(0xffffffffu, c0, 16);
            float t1 = __shfl_xor_sync(0xffffffffu, c1, 16);
            float t2 = __shfl_xor_sync(0xffffffffu, c2, 16);
            float t3 = __shfl_xor_sync(0xffffffffu, c3, 16);
            bool lo16 = lane < 16;
            float v = lo16 ? (c0 + t0) : (c1 + t1);
            float w = lo16 ? (c2 + t2) : (c3 + t3);
            float tv = __shfl_xor_sync(0xffffffffu, v, 8);
            float tw = __shfl_xor_sync(0xffffffffu, w, 8);
            float z = ((lane & 8) == 0) ? (v + tv) : (w + tw);
            z += __shfl_xor_sync(0xffffffffu, z, 4);
            z += __shfl_xor_sync(0xffffffffu, z, 2);
            z += __shfl_xor_sync(0xffffffffu, z, 1);

            if ((lane & 7) == 0) {
                int g = ((lane >> 2) & 2) | (lane >> 4);
                int idx = s0g + g;
                if (idx < total) out[idx] = z + b2s;
            }
        }
    }
}

extern "C" void kernel_launch(void* const* d_in, const int* in_sizes, int n_in,
                              void* d_out, int out_size) {
    const float* rec  = (const float*)d_in[0];
    const float* sloc = (const float*)d_in[1];
    const float* emit = (const float*)d_in[2];
    const float* rloc = (const float*)d_in[3];
    const float* W1   = (const float*)d_in[4];
    const float* b1v  = (const float*)d_in[5];
    const float* W2   = (const float*)d_in[6];
    const float* b2v  = (const float*)d_in[7];
    float* out = (float*)d_out;

    int nb1 = in_sizes[0] / (NUM_R * LREC);       // B1
    if (nb1 < 1) nb1 = 1;
    if (nb1 > MAXB1) nb1 = MAXB1;
    int total = out_size;                         // B1*B2 samples
    int b2n = total / nb1;

    int b1shift = -1;
    if (b2n > 0 && (b2n & (b2n - 1)) == 0) {
        b1shift = 0;
        while ((1 << b1shift) != b2n) ++b1shift;
    }

    prep_kernel<<<NUM_R, 256>>>(W1, rec, nb1);

    int blocks = (total + 63) / 64;               // 64 samples per block

    // PDL launch: tof's geometry overlaps prep; fallback to plain launch.
    cudaLaunchConfig_t cfg = {};
    cfg.gridDim  = dim3((unsigned)blocks, 1, 1);
    cfg.blockDim = dim3(256, 1, 1);
    cfg.dynamicSmemBytes = 0;
    cfg.stream = 0;
    cudaLaunchAttribute at[1];
    at[0].id = cudaLaunchAttributeProgrammaticStreamSerialization;
    at[0].val.programmaticStreamSerializationAllowed = 1;
    cfg.attrs = at;
    cfg.numAttrs = 1;
    cudaError_t e = cudaLaunchKernelEx(&cfg, tof_kernel,
                                       sloc, emit, rloc, b1v, W2, b2v, out,
                                       total, b2n, b1shift);
    if (e != cudaSuccess) {
        (void)cudaGetLastError();   // clear sticky error
        tof_kernel<<<blocks, 256>>>(sloc, emit, rloc, b1v, W2, b2v, out,
                                    total, b2n, b1shift);
    }
}